// round 12
// baseline (speedup 1.0000x reference)
#include <cuda_runtime.h>
#include <cuda_bf16.h>
#include <cstdint>

// Problem:
//   decoder_states: (32, 512, 1024) f32   d_in[0]
//   encoder_states: (32,1024, 1024) f32   d_in[1]
//   step:           scalar int (unused)   d_in[2]
//   mlp_weight:     (1, 2048) f32         d_in[3]  [0:1024]=w_enc, [1024:2048]=w_dec
//   mlp_bias:       (1,) f32              d_in[4]
//   out[b,t,s] = dot(dec[b,t], w_dec) + dot(enc[b,s], w_enc) + bias

#define DIM        1024
#define BATCH      32
#define T_DEC      512
#define S_ENC      1024
#define N_ENC_ROWS (BATCH * S_ENC)   // 32768

// Work items (same decomposition as R11):
//   producer item (b, p): 16 encoder rows  b*1024 + p*16 .. +15   (64/batch)
//   consumer item (b, c): 16 decoder rows + 16 out rows           (32/batch)
#define P_PER_BATCH 64
#define C_PER_BATCH 32
#define TOTAL_ITEMS (BATCH * (P_PER_BATCH + C_PER_BATCH))   // 3072
#define RPC 16

// Persistent grid: ~1 wave on 148 SMs at 8 CTAs/SM
#define PERSIST_BLOCKS 1184

// Scratch (allocation-free rule: __device__ globals; all self-resetting)
__device__ float g_enc_proj[N_ENC_ROWS];
__device__ int   g_pcnt[BATCH];   // producers done per batch
__device__ int   g_ccnt[BATCH];   // consumers done per batch (resets pcnt)
__device__ int   g_ticket;        // work dispenser
__device__ int   g_fin;           // blocks finished (resets ticket)

__device__ __forceinline__ float dot4(const float4 a, const float4 w, float s) {
    s = fmaf(a.x, w.x, s);
    s = fmaf(a.y, w.y, s);
    s = fmaf(a.z, w.z, s);
    return fmaf(a.w, w.w, s);
}

// Ticket -> (role, batch, idx) with a 2-batch producer lookahead:
// order: P(0), P(1), { P(k+2), C(k) } for k=0..29, C(30), C(31)
__device__ __forceinline__ void decode_item(int i, int& role, int& b, int& idx) {
    if (i < 2 * P_PER_BATCH) {                 // [0,128): producers batches 0,1
        role = 0; b = i >> 6; idx = i & 63;
    } else if (i < 2 * P_PER_BATCH + 30 * 96) {// [128,3008): interleaved
        const int j = (i - 128) / 96;
        const int r = (i - 128) - j * 96;
        if (r < P_PER_BATCH) { role = 0; b = j + 2; idx = r; }
        else                 { role = 1; b = j;     idx = r - P_PER_BATCH; }
    } else {                                   // [3008,3072): consumers 30,31
        const int k = i - 3008;
        role = 1; b = 30 + (k >> 5); idx = k & 31;
    }
}

__global__ __launch_bounds__(256)
void fused_persist(const float4* __restrict__ dec4,
                   const float4* __restrict__ enc4,
                   const float4* __restrict__ w4,    // full mlp_weight (2048 f32)
                   const float*  __restrict__ bias,
                   float4* __restrict__ out4)
{
    __shared__ int    s_item;
    __shared__ float4 esm[S_ENC / 4];   // 4 KB enc_proj row (consumer)
    __shared__ float  dsm[RPC];

    const int tid  = threadIdx.x;
    const int w    = tid >> 5;
    const int lane = tid & 31;

    for (;;) {
        if (tid == 0) s_item = atomicAdd(&g_ticket, 1);
        __syncthreads();                       // broadcast item; smem reuse fence
        const int i = s_item;
        if (i >= TOTAL_ITEMS) break;

        int role, b, idx;
        decode_item(i, role, b, idx);

        if (role == 0) {
            // ------------- producer: 16 encoder rows, warp-per-2-rows ------
            float4 W[8];
#pragma unroll
            for (int j = 0; j < 8; ++j) W[j] = __ldg(w4 + lane + 32 * j); // w_enc

            const int row0 = b * S_ENC + idx * 16 + 2 * w;
            const float4* __restrict__ src = enc4 + (size_t)row0 * (DIM / 4);

            float s0 = 0.f, s1 = 0.f;
#pragma unroll
            for (int j = 0; j < 8; ++j) {
                const int k = lane + 32 * j;
                const float4 a = __ldcs(src + k);
                const float4 c = __ldcs(src + 256 + k);
                s0 = dot4(a, W[j], s0);
                s1 = dot4(c, W[j], s1);
            }
#pragma unroll
            for (int off = 16; off > 0; off >>= 1) {
                s0 += __shfl_xor_sync(0xFFFFFFFFu, s0, off);
                s1 += __shfl_xor_sync(0xFFFFFFFFu, s1, off);
            }
            if (lane == 0) {
                g_enc_proj[row0]     = s0;
                g_enc_proj[row0 + 1] = s1;
            }
            __syncthreads();                   // all 16 rows written
            if (tid == 0) {
                __threadfence();               // release enc_proj writes
                atomicAdd(&g_pcnt[b], 1);
            }
        } else {
            // --------- consumer: 16 decoder rows + 16 output rows ----------
            const float bi = __ldg(bias);

            float4 W[8];
#pragma unroll
            for (int j = 0; j < 8; ++j)
                W[j] = __ldg(w4 + (DIM / 4) + lane + 32 * j);   // w_dec

            const int t0  = idx * RPC;
            const int row = b * T_DEC + t0 + 2 * w;
            const float4* __restrict__ src = dec4 + (size_t)row * (DIM / 4);

            float s0 = 0.f, s1 = 0.f;
#pragma unroll
            for (int j = 0; j < 8; ++j) {
                const int k = lane + 32 * j;
                const float4 a = __ldcs(src + k);
                const float4 c = __ldcs(src + 256 + k);
                s0 = dot4(a, W[j], s0);
                s1 = dot4(c, W[j], s1);
            }
#pragma unroll
            for (int off = 16; off > 0; off >>= 1) {
                s0 += __shfl_xor_sync(0xFFFFFFFFu, s0, off);
                s1 += __shfl_xor_sync(0xFFFFFFFFu, s1, off);
            }
            if (lane == 0) {
                dsm[2 * w]     = s0 + bi;
                dsm[2 * w + 1] = s1 + bi;
            }

            // gate (should be nearly free: producers had a 2-batch head start)
            if (tid == 0) {
                while (((volatile int*)g_pcnt)[b] != P_PER_BATCH) __nanosleep(64);
                __threadfence();               // acquire
            }
            __syncthreads();

            esm[tid] = ((const float4*)g_enc_proj)[b * (S_ENC / 4) + tid];
            __syncthreads();

            const float4 e = esm[tid];
            float4* __restrict__ obase =
                out4 + (size_t)(b * T_DEC + t0) * (DIM / 4) + tid;
#pragma unroll
            for (int rr = 0; rr < RPC; ++rr) {
                const float d = dsm[rr];
                float4 o;
                o.x = d + e.x; o.y = d + e.y; o.z = d + e.z; o.w = d + e.w;
                __stcs(obase + (size_t)rr * (DIM / 4), o);
            }

            // last consumer of batch b resets that batch's counters
            if (tid == 0) {
                const int done = atomicAdd(&g_ccnt[b], 1);
                if (done == C_PER_BATCH - 1) {
                    g_pcnt[b] = 0;
                    g_ccnt[b] = 0;
                }
            }
        }
    }

    // self-reset of the dispenser: last block to finish zeroes ticket + fin
    if (tid == 0) {
        const int f = atomicAdd(&g_fin, 1);
        if (f == PERSIST_BLOCKS - 1) {
            g_ticket = 0;
            g_fin    = 0;
        }
    }
}

extern "C" void kernel_launch(void* const* d_in, const int* in_sizes, int n_in,
                              void* d_out, int out_size)
{
    const float4* dec4 = (const float4*)d_in[0];
    const float4* enc4 = (const float4*)d_in[1];
    // d_in[2] = step (unused)
    const float4* w4   = (const float4*)d_in[3];
    const float*  bias = (const float*)d_in[4];
    float4* out4 = (float4*)d_out;

    fused_persist<<<PERSIST_BLOCKS, 256>>>(dec4, enc4, w4, bias, out4);
}

// round 13
// speedup vs baseline: 1.0773x; 1.0773x over previous
#include <cuda_runtime.h>
#include <cuda_bf16.h>
#include <cstdint>

// Problem:
//   decoder_states: (32, 512, 1024) f32   d_in[0]
//   encoder_states: (32,1024, 1024) f32   d_in[1]
//   step:           scalar int (unused)   d_in[2]
//   mlp_weight:     (1, 2048) f32         d_in[3]  [0:1024]=w_enc, [1024:2048]=w_dec
//   mlp_bias:       (1,) f32              d_in[4]
//   out[b,t,s] = dot(dec[b,t], w_dec) + dot(enc[b,s], w_enc) + bias

#define DIM        1024
#define BATCH      32
#define T_DEC      512
#define S_ENC      1024
#define N_ENC_ROWS (BATCH * S_ENC)   // 32768

// Per batch: 128 producers (8 enc rows each, warp-per-row) + 32 consumers
// (16 dec rows + 16 out rows). Producer items are HALF the consumer pre-gate
// work, so the last producer of a batch retires before consumers reach the
// gate even with ~2x per-CTA completion spread -> gate wait ~ 0.
#define P_PER_BATCH 128
#define C_PER_BATCH 32
#define BLK_PER_BATCH (P_PER_BATCH + C_PER_BATCH)   // 160
#define GRID (BATCH * BLK_PER_BATCH)                // 5120
#define RPC 16   // decoder/output rows per consumer

// Scratch (allocation-free rule: __device__ globals; self-resetting counters)
__device__ float g_enc_proj[N_ENC_ROWS];
__device__ int   g_pcnt[BATCH];   // producers done per batch
__device__ int   g_ccnt[BATCH];   // consumers done per batch (resets pcnt)

__device__ __forceinline__ float dot4(const float4 a, const float4 w, float s) {
    s = fmaf(a.x, w.x, s);
    s = fmaf(a.y, w.y, s);
    s = fmaf(a.z, w.z, s);
    return fmaf(a.w, w.w, s);
}

// ---------------------------------------------------------------------------
// Merged producer/consumer kernel, batch-major block order:
//   bid = b*160 + r :  r < 128 -> producer (enc rows b*1024 + r*8 .. +7)
//                      r >= 128 -> consumer (dec rows b*512 + (r-128)*16 ..)
// Consumers compute their decoder dots FIRST (overlapping the enc read
// stream), then gate on g_pcnt[b]==128, then broadcast-store 16 rows.
// Deadlock-free: consumers wait only on lower-bid producers; producers never
// wait; CTA admission is bid-ordered.
// ---------------------------------------------------------------------------
__global__ __launch_bounds__(256)
void fused_all(const float4* __restrict__ dec4,
               const float4* __restrict__ enc4,
               const float4* __restrict__ w4,    // full mlp_weight (2048 f32)
               const float*  __restrict__ bias,
               float4* __restrict__ out4)
{
    const int bid  = blockIdx.x;
    const int b    = bid / BLK_PER_BATCH;
    const int r    = bid - b * BLK_PER_BATCH;
    const int tid  = threadIdx.x;
    const int w    = tid >> 5;
    const int lane = tid & 31;

    if (r < P_PER_BATCH) {
        // ---------------- producer: 8 encoder rows, warp-per-row -----------
        float4 W[8];
#pragma unroll
        for (int j = 0; j < 8; ++j) W[j] = __ldg(w4 + lane + 32 * j);   // w_enc

        const int row = b * S_ENC + r * 8 + w;   // warp w -> one row
        const float4* __restrict__ src = enc4 + (size_t)row * (DIM / 4);

        float acc = 0.f;
#pragma unroll
        for (int j = 0; j < 8; ++j)
            acc = dot4(__ldcs(src + lane + 32 * j), W[j], acc);
#pragma unroll
        for (int off = 16; off > 0; off >>= 1)
            acc += __shfl_xor_sync(0xFFFFFFFFu, acc, off);

        if (lane == 0) g_enc_proj[row] = acc;
        __syncthreads();                       // all 8 rows written
        if (tid == 0) {
            __threadfence();                   // release enc_proj writes
            atomicAdd(&g_pcnt[b], 1);
        }
    } else {
        // ------------ consumer: 16 decoder rows + 16 output rows -----------
        __shared__ float4 esm[S_ENC / 4];      // 4 KB enc_proj row of batch b
        __shared__ float  dsm[RPC];

        const float bi = __ldg(bias);

        float4 W[8];
#pragma unroll
        for (int j = 0; j < 8; ++j)
            W[j] = __ldg(w4 + (DIM / 4) + lane + 32 * j);   // w_dec

        const int t0  = (r - P_PER_BATCH) * RPC;
        const int row = b * T_DEC + t0 + 2 * w;   // warp w -> rows t0+2w, +1
        const float4* __restrict__ src = dec4 + (size_t)row * (DIM / 4);

        // decoder dots first: 64 KB pre-gate work, overlaps producer reads
        float s0 = 0.f, s1 = 0.f;
#pragma unroll
        for (int j = 0; j < 8; ++j) {
            const int idx = lane + 32 * j;
            const float4 a = __ldcs(src + idx);
            const float4 c = __ldcs(src + 256 + idx);
            s0 = dot4(a, W[j], s0);
            s1 = dot4(c, W[j], s1);
        }
#pragma unroll
        for (int off = 16; off > 0; off >>= 1) {
            s0 += __shfl_xor_sync(0xFFFFFFFFu, s0, off);
            s1 += __shfl_xor_sync(0xFFFFFFFFu, s1, off);
        }
        if (lane == 0) {
            dsm[2 * w]     = s0 + bi;
            dsm[2 * w + 1] = s1 + bi;
        }

        // gate: wait for this batch's 128 producers (expected ~free)
        if (tid == 0) {
            while (((volatile int*)g_pcnt)[b] != P_PER_BATCH) __nanosleep(64);
            __threadfence();                   // acquire
        }
        __syncthreads();

        esm[tid] = ((const float4*)g_enc_proj)[b * (S_ENC / 4) + tid];
        __syncthreads();

        const float4 e = esm[tid];
        float4* __restrict__ obase =
            out4 + (size_t)(b * T_DEC + t0) * (DIM / 4) + tid;
#pragma unroll
        for (int rr = 0; rr < RPC; ++rr) {
            const float d = dsm[rr];
            float4 o;
            o.x = d + e.x; o.y = d + e.y; o.z = d + e.z; o.w = d + e.w;
            __stcs(obase + (size_t)rr * (DIM / 4), o);
        }

        // self-reset: last consumer through zeroes both counters so the next
        // graph replay starts clean (no reset kernel needed).
        if (tid == 0) {
            const int done = atomicAdd(&g_ccnt[b], 1);
            if (done == C_PER_BATCH - 1) {
                g_pcnt[b] = 0;
                g_ccnt[b] = 0;
            }
        }
    }
}

extern "C" void kernel_launch(void* const* d_in, const int* in_sizes, int n_in,
                              void* d_out, int out_size)
{
    const float4* dec4 = (const float4*)d_in[0];
    const float4* enc4 = (const float4*)d_in[1];
    // d_in[2] = step (unused)
    const float4* w4   = (const float4*)d_in[3];
    const float*  bias = (const float*)d_in[4];
    float4* out4 = (float4*)d_out;

    fused_all<<<GRID, 256>>>(dec4, enc4, w4, bias, out4);
}